// round 2
// baseline (speedup 1.0000x reference)
#include <cuda_runtime.h>
#include <mma.h>
#include <math.h>

using namespace nvcuda;

#define NTOK 8192
#define DIM  1024
#define NE   8
#define HIDN 2048
#define TWOH 4096
#define NSLOT (NTOK*2)

// ---- scratch (allocation-free: __device__ globals) ----
__device__ int   g_cnt[NE];
__device__ int   g_off[NE];
__device__ int   g_list[NE*NTOK];
__device__ float g_scl[NE*NTOK];
__device__ float g_psum[NE];
__device__ float g_gbuf[(size_t)NSLOT * HIDN];   // 16384 x 2048 fp32 = 128 MB

// =====================================================================
// init
// =====================================================================
__global__ void zero_small_kernel() {
    int t = threadIdx.x;
    if (t < NE) { g_cnt[t] = 0; g_psum[t] = 0.f; }
}

__global__ void zero_out_kernel(float* __restrict__ out) {
    size_t idx = (size_t)blockIdx.x * blockDim.x + threadIdx.x;   // 8192*256 = 2M float4
    float4 z = make_float4(0.f, 0.f, 0.f, 0.f);
    ((float4*)out)[idx] = z;
}

// =====================================================================
// router: 1 warp per token
// =====================================================================
__global__ void router_kernel(const float* __restrict__ x,
                              const float* __restrict__ Wr,
                              const float* __restrict__ br) {
    __shared__ float sp[NE];
    int tid = threadIdx.x;
    if (tid < NE) sp[tid] = 0.f;
    __syncthreads();

    int warp = tid >> 5, lane = tid & 31;
    int t = blockIdx.x * 8 + warp;

    float acc[NE];
#pragma unroll
    for (int e = 0; e < NE; e++) acc[e] = 0.f;

    const float* xr = x + (size_t)t * DIM;
    for (int d = lane; d < DIM; d += 32) {
        float xv = xr[d];
        const float* w = Wr + d * NE;
#pragma unroll
        for (int e = 0; e < NE; e++) acc[e] += xv * w[e];
    }
#pragma unroll
    for (int o = 16; o; o >>= 1)
#pragma unroll
        for (int e = 0; e < NE; e++) acc[e] += __shfl_down_sync(0xffffffffu, acc[e], o);

    if (lane == 0) {
        float l[NE];
        float m = -1e30f;
#pragma unroll
        for (int e = 0; e < NE; e++) { l[e] = acc[e] + br[e]; m = fmaxf(m, l[e]); }
        float s = 0.f, p[NE];
#pragma unroll
        for (int e = 0; e < NE; e++) { p[e] = __expf(l[e] - m); s += p[e]; }
        float inv = 1.f / s;
#pragma unroll
        for (int e = 0; e < NE; e++) atomicAdd(&sp[e], p[e] * inv);

        // top-2 (strict > matches jax lowest-index tie-break)
        int i0 = 0; float v0 = l[0];
#pragma unroll
        for (int e = 1; e < NE; e++) if (l[e] > v0) { v0 = l[e]; i0 = e; }
        int i1 = -1; float v1 = -1e30f;
#pragma unroll
        for (int e = 0; e < NE; e++) if (e != i0 && l[e] > v1) { v1 = l[e]; i1 = e; }

        float sc0 = 1.f / (1.f + __expf(v1 - v0));   // softmax over [v0,v1]
        float sc1 = 1.f - sc0;

        int p0 = atomicAdd(&g_cnt[i0], 1);
        g_list[i0 * NTOK + p0] = t;  g_scl[i0 * NTOK + p0] = sc0;
        int p1 = atomicAdd(&g_cnt[i1], 1);
        g_list[i1 * NTOK + p1] = t;  g_scl[i1 * NTOK + p1] = sc1;
    }
    __syncthreads();
    if (tid < NE) atomicAdd(&g_psum[tid], sp[tid]);
}

// prefix offsets + aux loss
__global__ void finalize_router(float* __restrict__ out) {
    int off = 0;
    float aux = 0.f;
    for (int e = 0; e < NE; e++) {
        g_off[e] = off;
        off += g_cnt[e];
        float f = (float)g_cnt[e] / (float)NTOK;
        float p = g_psum[e] / (float)NTOK;
        aux += f * p;
    }
    out[(size_t)NTOK * DIM] = aux * (float)NE;
}

// =====================================================================
// GEMM1: g[slot, c] = silu(x@W1[:, c]+b1a) * (x@W1[:, c+2048]+b1b)
// block: 128 rows x 64 cols (dual accumulator for the gate pair)
// grid: (mtile[64], ctile[32], expert[8])  -- mtile fastest for W1 L2 reuse
// =====================================================================
#define LDA 36
#define LDB 68
#define LDC 68

__global__ void gemm1_kernel(const float* __restrict__ x,
                             const float* __restrict__ W1,
                             const float* __restrict__ b1) {
    int e = blockIdx.z;
    int cnt = g_cnt[e];
    int mbase = blockIdx.x * 128;
    if (mbase >= cnt) return;
    int base = g_off[e];
    int c0 = blockIdx.y * 64;

    extern __shared__ float sm[];
    float* As = sm;                 // [128][36]
    float* Ba = sm + 128 * LDA;     // [32][68]
    float* Bb = Ba + 32 * LDB;      // [32][68]
    __shared__ int s_tok[128];

    int tid = threadIdx.x;
    if (tid < 128) {
        int r = mbase + tid;
        s_tok[tid] = (r < cnt) ? g_list[e * NTOK + r] : -1;
    }
    __syncthreads();

    wmma::fragment<wmma::accumulator, 16, 16, 8, float> accA[2][2], accB[2][2];
#pragma unroll
    for (int i = 0; i < 2; i++)
#pragma unroll
        for (int j = 0; j < 2; j++) {
            wmma::fill_fragment(accA[i][j], 0.f);
            wmma::fill_fragment(accB[i][j], 0.f);
        }

    int wid = tid >> 5;
    int wr = wid >> 1;          // 0..3  (32-row slab)
    int wc = wid & 1;           // 0..1  (32-col slab)

    const float* W1e = W1 + (size_t)e * DIM * TWOH;

    for (int k0 = 0; k0 < DIM; k0 += 32) {
        // A tile: 128x32, gathered rows
#pragma unroll
        for (int i = 0; i < 4; i++) {
            int idx = tid + i * 256;           // 0..1023
            int row = idx >> 3, c4 = (idx & 7) << 2;
            int tok = s_tok[row];
            float4 v = make_float4(0.f, 0.f, 0.f, 0.f);
            if (tok >= 0) v = *(const float4*)(x + (size_t)tok * DIM + k0 + c4);
            float* dst = As + row * LDA + c4;
            dst[0] = v.x; dst[1] = v.y; dst[2] = v.z; dst[3] = v.w;
        }
        // B tiles: 32x64 each, cols [c0,c0+64) and [c0+2048, ...)
#pragma unroll
        for (int i = 0; i < 2; i++) {
            int idx = tid + i * 256;           // 0..511
            int kr = idx >> 4, c4 = (idx & 15) << 2;
            const float* src = W1e + (size_t)(k0 + kr) * TWOH + c0 + c4;
            float4 va = *(const float4*)src;
            float4 vb = *(const float4*)(src + HIDN);
            float* da = Ba + kr * LDB + c4;
            da[0] = va.x; da[1] = va.y; da[2] = va.z; da[3] = va.w;
            float* db = Bb + kr * LDB + c4;
            db[0] = vb.x; db[1] = vb.y; db[2] = vb.z; db[3] = vb.w;
        }
        __syncthreads();

#pragma unroll
        for (int ks = 0; ks < 4; ks++) {
            int kk = ks * 8;
            wmma::fragment<wmma::matrix_a, 16, 16, 8, wmma::precision::tf32, wmma::row_major> af[2];
#pragma unroll
            for (int i = 0; i < 2; i++) {
                wmma::load_matrix_sync(af[i], As + (wr * 32 + i * 16) * LDA + kk, LDA);
#pragma unroll
                for (int u = 0; u < af[i].num_elements; u++)
                    af[i].x[u] = wmma::__float_to_tf32(af[i].x[u]);
            }
            wmma::fragment<wmma::matrix_b, 16, 16, 8, wmma::precision::tf32, wmma::row_major> bfA[2], bfB[2];
#pragma unroll
            for (int j = 0; j < 2; j++) {
                wmma::load_matrix_sync(bfA[j], Ba + kk * LDB + wc * 32 + j * 16, LDB);
                wmma::load_matrix_sync(bfB[j], Bb + kk * LDB + wc * 32 + j * 16, LDB);
#pragma unroll
                for (int u = 0; u < bfA[j].num_elements; u++) {
                    bfA[j].x[u] = wmma::__float_to_tf32(bfA[j].x[u]);
                    bfB[j].x[u] = wmma::__float_to_tf32(bfB[j].x[u]);
                }
            }
#pragma unroll
            for (int i = 0; i < 2; i++)
#pragma unroll
                for (int j = 0; j < 2; j++) {
                    wmma::mma_sync(accA[i][j], af[i], bfA[j], accA[i][j]);
                    wmma::mma_sync(accB[i][j], af[i], bfB[j], accB[i][j]);
                }
        }
        __syncthreads();
    }

    // epilogue: stage both halves, fuse SiLU-gate
    float* bufA = sm;                  // [128][68]
    float* bufB = sm + 128 * LDC;      // [128][68]
#pragma unroll
    for (int i = 0; i < 2; i++)
#pragma unroll
        for (int j = 0; j < 2; j++) {
            wmma::store_matrix_sync(bufA + (wr * 32 + i * 16) * LDC + wc * 32 + j * 16,
                                    accA[i][j], LDC, wmma::mem_row_major);
            wmma::store_matrix_sync(bufB + (wr * 32 + i * 16) * LDC + wc * 32 + j * 16,
                                    accB[i][j], LDC, wmma::mem_row_major);
        }
    __syncthreads();

    const float* b1a = b1 + (size_t)e * TWOH + c0;
    const float* b1b = b1a + HIDN;
    int mlim = min(128, cnt - mbase);
    for (int idx = tid; idx < 128 * 64; idx += 256) {
        int row = idx >> 6, c = idx & 63;
        if (row < mlim) {
            float a = bufA[row * LDC + c] + b1a[c];
            float b = bufB[row * LDC + c] + b1b[c];
            float gv = a * (1.f / (1.f + __expf(-a))) * b;
            g_gbuf[(size_t)(base + mbase + row) * HIDN + c0 + c] = gv;
        }
    }
}

// =====================================================================
// GEMM2: out[token] += score * (g @ W2[e] + b2[e])
// grid: (mtile[64], ctile[16], expert[8])
// =====================================================================
__global__ void gemm2_kernel(const float* __restrict__ W2,
                             const float* __restrict__ b2,
                             float* __restrict__ out) {
    int e = blockIdx.z;
    int cnt = g_cnt[e];
    int mbase = blockIdx.x * 128;
    if (mbase >= cnt) return;
    int base = g_off[e];
    int c0 = blockIdx.y * 64;

    extern __shared__ float sm[];
    float* As = sm;                 // [128][36]
    float* Bs = sm + 128 * LDA;     // [32][68]
    __shared__ int   s_tok[128];
    __shared__ float s_scl[128];

    int tid = threadIdx.x;
    int mlim = min(128, cnt - mbase);
    if (tid < 128) {
        int r = mbase + tid;
        if (r < cnt) {
            s_tok[tid] = g_list[e * NTOK + r];
            s_scl[tid] = g_scl[e * NTOK + r];
        } else { s_tok[tid] = -1; s_scl[tid] = 0.f; }
    }
    __syncthreads();

    wmma::fragment<wmma::accumulator, 16, 16, 8, float> acc[2][2];
#pragma unroll
    for (int i = 0; i < 2; i++)
#pragma unroll
        for (int j = 0; j < 2; j++) wmma::fill_fragment(acc[i][j], 0.f);

    int wid = tid >> 5;
    int wr = wid >> 1, wc = wid & 1;

    const float* W2e = W2 + (size_t)e * HIDN * DIM;
    const float* Ag  = g_gbuf + (size_t)(base + mbase) * HIDN;

    for (int k0 = 0; k0 < HIDN; k0 += 32) {
#pragma unroll
        for (int i = 0; i < 4; i++) {
            int idx = tid + i * 256;
            int row = idx >> 3, c4 = (idx & 7) << 2;
            float4 v = make_float4(0.f, 0.f, 0.f, 0.f);
            if (row < mlim) v = *(const float4*)(Ag + (size_t)row * HIDN + k0 + c4);
            float* dst = As + row * LDA + c4;
            dst[0] = v.x; dst[1] = v.y; dst[2] = v.z; dst[3] = v.w;
        }
#pragma unroll
        for (int i = 0; i < 1; i++) {
            int idx = tid;                      // 0..255 covers 32x64/4=512? no: 2 per thread below
            (void)idx;
        }
#pragma unroll
        for (int i = 0; i < 2; i++) {
            int idx = tid + i * 256;            // 0..511
            int kr = idx >> 4, c4 = (idx & 15) << 2;
            const float* src = W2e + (size_t)(k0 + kr) * DIM + c0 + c4;
            float4 v = *(const float4*)src;
            float* dst = Bs + kr * LDB + c4;
            dst[0] = v.x; dst[1] = v.y; dst[2] = v.z; dst[3] = v.w;
        }
        __syncthreads();

#pragma unroll
        for (int ks = 0; ks < 4; ks++) {
            int kk = ks * 8;
            wmma::fragment<wmma::matrix_a, 16, 16, 8, wmma::precision::tf32, wmma::row_major> af[2];
#pragma unroll
            for (int i = 0; i < 2; i++) {
                wmma::load_matrix_sync(af[i], As + (wr * 32 + i * 16) * LDA + kk, LDA);
#pragma unroll
                for (int u = 0; u < af[i].num_elements; u++)
                    af[i].x[u] = wmma::__float_to_tf32(af[i].x[u]);
            }
            wmma::fragment<wmma::matrix_b, 16, 16, 8, wmma::precision::tf32, wmma::row_major> bf[2];
#pragma unroll
            for (int j = 0; j < 2; j++) {
                wmma::load_matrix_sync(bf[j], Bs + kk * LDB + wc * 32 + j * 16, LDB);
#pragma unroll
                for (int u = 0; u < bf[j].num_elements; u++)
                    bf[j].x[u] = wmma::__float_to_tf32(bf[j].x[u]);
            }
#pragma unroll
            for (int i = 0; i < 2; i++)
#pragma unroll
                for (int j = 0; j < 2; j++)
                    wmma::mma_sync(acc[i][j], af[i], bf[j], acc[i][j]);
        }
        __syncthreads();
    }

    float* buf = sm;                   // [128][68]
#pragma unroll
    for (int i = 0; i < 2; i++)
#pragma unroll
        for (int j = 0; j < 2; j++)
            wmma::store_matrix_sync(buf + (wr * 32 + i * 16) * LDC + wc * 32 + j * 16,
                                    acc[i][j], LDC, wmma::mem_row_major);
    __syncthreads();

    const float* b2e = b2 + (size_t)e * DIM + c0;
    for (int idx = tid; idx < 128 * 64; idx += 256) {
        int row = idx >> 6, c = idx & 63;
        if (row < mlim) {
            float v = buf[row * LDC + c] + b2e[c];
            atomicAdd(&out[(size_t)s_tok[row] * DIM + c0 + c], s_scl[row] * v);
        }
    }
}

// =====================================================================
// launch
// =====================================================================
extern "C" void kernel_launch(void* const* d_in, const int* in_sizes, int n_in,
                              void* d_out, int out_size) {
    const float* x  = (const float*)d_in[0];
    const float* Wr = (const float*)d_in[1];
    const float* br = (const float*)d_in[2];
    const float* W1 = (const float*)d_in[3];
    const float* b1 = (const float*)d_in[4];
    const float* W2 = (const float*)d_in[5];
    const float* b2 = (const float*)d_in[6];
    float* out = (float*)d_out;

    static const int SMEM1 = (128 * LDC * 2) * 4;            // 69632 B (epilogue dominates)
    static const int SMEM2 = (128 * LDC) * 4;                // 34816 B
    cudaFuncSetAttribute(gemm1_kernel, cudaFuncAttributeMaxDynamicSharedMemorySize, SMEM1);
    cudaFuncSetAttribute(gemm2_kernel, cudaFuncAttributeMaxDynamicSharedMemorySize, SMEM2);

    zero_small_kernel<<<1, 32>>>();
    zero_out_kernel<<<8192, 256>>>(out);                      // zeros exactly NTOK*DIM floats
    router_kernel<<<NTOK / 8, 256>>>(x, Wr, br);
    finalize_router<<<1, 1>>>(out);
    gemm1_kernel<<<dim3(64, 32, 8), 256, SMEM1>>>(x, W1, b1);
    gemm2_kernel<<<dim3(64, 16, 8), 256, SMEM2>>>(W2, b2, out);
}